// round 6
// baseline (speedup 1.0000x reference)
#include <cuda_runtime.h>

// ---------------------------------------------------------------------------
// ResonantComplexProjection
//   theta[b,n,i] = x[b,i] / (1+|W[n,i]|) + B[n,i]
//   idx = floor(theta * 4096/2pi) mod 4096   (LUT sin/cos, 4096 entries)
//   cos_sum[b,n] = sum_i cos_lut[idx];  sin_sum likewise
//   real = cos_sum @ Wr^T ; imag = sin_sum @ Wi^T
// Shapes: batch=256, in_f=512, n_neur=1024, out_f=512
// ---------------------------------------------------------------------------

#define LUT_HALF 4608                 // table covers k in [-4608, 4608)
#define LUT_N    (2 * LUT_HALF)       // 9216 entries (float2: sin, cos)
#define SMEM_MAIN (LUT_N * 8 + 8192)  // 72KB LUT + 8KB x tile = 81920 B

static __device__ float4 g_lut4[LUT_N / 2];       // 2 (sin,cos) entries per float4
static __device__ float2 g_rs[256 * 1024];        // [ipair][n] -> {S/(1+|W|)}
static __device__ float2 g_bs[256 * 1024];        // [ipair][n] -> {S*B - 0.5}
static __device__ float2 g_sums[2 * 256 * 1024];  // [half][b][n] -> (sin_sum, cos_sum)
static __device__ float  g_A[2 * 262144];         // [p][b][k]: p0=cos, p1=sin (halves combined)
static __device__ float  g_part[4][262144];       // [ksplit][p*131072 + b*512 + o]

// ---------------------------------------------------------------------------
// Init kernels
// ---------------------------------------------------------------------------

__global__ void k_init_lut() {
    int t = blockIdx.x * 256 + threadIdx.x;       // < 4608
    const float step = (float)(6.283185307179586476925287 / 4096.0);
    int k0 = 2 * t - LUT_HALF;
    int j0 = k0 & 4095;                            // floor-mod 4096 (matches Python %)
    int j1 = (k0 + 1) & 4095;
    float a0 = (float)j0 * step;
    float a1 = (float)j1 * step;
    float4 e;
    e.x = sinf(a0); e.y = cosf(a0);
    e.z = sinf(a1); e.w = cosf(a1);
    g_lut4[t] = e;
}

__global__ void k_init_rb(const float* __restrict__ W, const float* __restrict__ B) {
    int e = blockIdx.x * 256 + threadIdx.x;       // < 262144
    int n  = e & 1023;
    int ip = e >> 10;
    const float S = (float)(4096.0 / 6.283185307179586476925287);
    float2 w = ((const float2*)(W + n * 512))[ip];
    float2 b = ((const float2*)(B + n * 512))[ip];
    float2 rs, bs;
    rs.x = S / (1.0f + fabsf(w.x));
    rs.y = S / (1.0f + fabsf(w.y));
    bs.x = S * b.x - 0.5f;                        // fold floor(v)=round(v-0.5) shift in
    bs.y = S * b.y - 0.5f;
    g_rs[e] = rs;
    g_bs[e] = bs;
}

// ---------------------------------------------------------------------------
// Packed f32x2 helpers
// ---------------------------------------------------------------------------

__device__ __forceinline__ unsigned long long fma2_(unsigned long long a,
                                                    unsigned long long b,
                                                    unsigned long long c) {
    unsigned long long d;
    asm("fma.rn.f32x2 %0, %1, %2, %3;" : "=l"(d) : "l"(a), "l"(b), "l"(c));
    return d;
}
__device__ __forceinline__ unsigned long long add2_(unsigned long long a,
                                                    unsigned long long b) {
    unsigned long long d;
    asm("add.rn.f32x2 %0, %1, %2;" : "=l"(d) : "l"(a), "l"(b));
    return d;
}
__device__ __forceinline__ unsigned long long lds64_(unsigned a) {
    unsigned long long v;
    asm("ld.shared.b64 %0, [%1];" : "=l"(v) : "r"(a));
    return v;
}

// ---------------------------------------------------------------------------
// Main kernel (UNCHANGED — proven): grid (4 n-tiles, 32 b-groups, 2 i-halves).
// Magic-number floor + extended shared LUT; packed f32x2 accumulation.
// ---------------------------------------------------------------------------

__global__ __launch_bounds__(256, 2) void k_main(const float* __restrict__ x) {
    extern __shared__ unsigned char smem[];
    float4* lut4 = (float4*)smem;
    unsigned long long* xs2 = (unsigned long long*)(smem + LUT_N * 8);  // [8 b][128 ipair]

    const int tid = threadIdx.x;
    const int nt = blockIdx.x, bg = blockIdx.y, h = blockIdx.z;

#pragma unroll
    for (int t = 0; t < (LUT_N / 2) / 256; t++)        // stage 72KB LUT
        lut4[tid + t * 256] = g_lut4[tid + t * 256];

    const unsigned long long* xg = (const unsigned long long*)x;
#pragma unroll
    for (int t = 0; t < 4; t++) {
        int e = tid + t * 256;
        int lb = e >> 7, ipl = e & 127;
        xs2[e] = xg[(bg * 8 + lb) * 256 + h * 128 + ipl];
    }
    __syncthreads();

    const int n = (nt << 8) + tid;
    const unsigned long long* rsp =
        ((const unsigned long long*)g_rs) + (size_t)(h * 128) * 1024 + n;
    const unsigned long long* bsp =
        ((const unsigned long long*)g_bs) + (size_t)(h * 128) * 1024 + n;

    const unsigned cbase =
        (unsigned)__cvta_generic_to_shared(smem) + (unsigned)(LUT_HALF * 8) - 0x5A000000u;
    const unsigned long long MAGIC2 = 0x4B4000004B400000ULL;

    unsigned long long acc[8];
#pragma unroll
    for (int b = 0; b < 8; b++) acc[b] = 0ULL;

#pragma unroll 2
    for (int ip = 0; ip < 128; ip++) {
        unsigned long long rs2 = __ldg(rsp + ip * 1024);
        unsigned long long bs2 = __ldg(bsp + ip * 1024);
#pragma unroll
        for (int b = 0; b < 8; b++) {
            unsigned long long xp = xs2[b * 128 + ip];
            unsigned long long w  = add2_(fma2_(xp, rs2, bs2), MAGIC2);
            unsigned lo, hi;
            asm("mov.b64 {%0, %1}, %2;" : "=r"(lo), "=r"(hi) : "l"(w));
            unsigned long long e0 = lds64_(lo * 8u + cbase);
            unsigned long long e1 = lds64_(hi * 8u + cbase);
            acc[b] = add2_(acc[b], e0);
            acc[b] = add2_(acc[b], e1);
        }
    }

    unsigned long long* sp =
        ((unsigned long long*)g_sums) + (size_t)h * 262144 + (size_t)(bg * 8) * 1024 + n;
#pragma unroll
    for (int b = 0; b < 8; b++) sp[b * 1024] = acc[b];
}

// ---------------------------------------------------------------------------
// k_comb: combine the two i-half partials ONCE and split into cos/sin planes.
// g_A[0][b][k] = cos_sum, g_A[1][b][k] = sin_sum. (Was done 16x redundantly.)
// ---------------------------------------------------------------------------

__global__ void k_comb() {
    int e = blockIdx.x * 256 + threadIdx.x;            // < 131072, 2 entries each
    float4 q0 = ((const float4*)g_sums)[e];            // h0: {s0,c0,s1,c1}
    float4 q1 = ((const float4*)(g_sums + 262144))[e]; // h1
    ((float2*)g_A)[e]            = make_float2(q0.y + q1.y, q0.w + q1.w); // cos
    ((float2*)(g_A + 262144))[e] = make_float2(q0.x + q1.x, q0.z + q1.z); // sin
}

// ---------------------------------------------------------------------------
// k_gemm3: split-K GEMM with packed f32x2 FMA + single-sync double buffering.
//   Block: 64x64 tile of one plane (p) and one K-split of 256 (s).
//   grid (4 b-tiles, 8 o-tiles, 8 = p*4+s) = 256 blocks, 256 threads.
//   A staged DUPLICATED in smem ({a,a} pairs) so the inner loop is pure:
//     3 LDS.128 + 8 fma.rn.f32x2 per kk  (32 MACs per 11 issues).
// ---------------------------------------------------------------------------

#define GPA 132   // AsD row stride in floats (128 data + 4 pad; float4-aligned, 2-way STS max)
#define GPB 68    // Bs row stride in floats

__global__ __launch_bounds__(256, 2) void k_gemm3(const float* __restrict__ Wr,
                                                  const float* __restrict__ Wi) {
    __shared__ float AsD[2][16 * GPA];   // [stage][kk][2m] duplicated A
    __shared__ float Bs [2][16 * GPB];   // [stage][kk][o]

    const int tid = threadIdx.x;
    const int b0 = blockIdx.x << 6;
    const int o0 = blockIdx.y << 6;
    const int z  = blockIdx.z;
    const int pp = z >> 2;               // 0=real(cos), 1=imag(sin)
    const int s  = z & 3;                // K-split (256 each)

    const float* Ap = g_A + pp * 262144;
    const float* Wp = pp ? Wi : Wr;

    const int tx = tid & 15, ty = tid >> 4;
    const int lm = tid >> 2;             // loader row 0..63
    const int lq = (tid & 3) << 2;       // loader k-quad offset {0,4,8,12}

    const float4* ga = (const float4*)(Ap + (size_t)(b0 + lm) * 1024 + (s << 8) + lq);
    const float4* gw = (const float4*)(Wp + (size_t)(o0 + lm) * 1024 + (s << 8) + lq);

    unsigned long long acc[4][2];
#pragma unroll
    for (int i = 0; i < 4; i++) { acc[i][0] = 0ULL; acc[i][1] = 0ULL; }

    // --- stage 0 load ---
    float4 a4 = ga[0];
    float4 w4 = gw[0];
    {
        float* A0 = AsD[0]; float* B0 = Bs[0];
        *(float2*)&A0[(lq + 0) * GPA + 2 * lm] = make_float2(a4.x, a4.x);
        *(float2*)&A0[(lq + 1) * GPA + 2 * lm] = make_float2(a4.y, a4.y);
        *(float2*)&A0[(lq + 2) * GPA + 2 * lm] = make_float2(a4.z, a4.z);
        *(float2*)&A0[(lq + 3) * GPA + 2 * lm] = make_float2(a4.w, a4.w);
        B0[(lq + 0) * GPB + lm] = w4.x;
        B0[(lq + 1) * GPB + lm] = w4.y;
        B0[(lq + 2) * GPB + lm] = w4.z;
        B0[(lq + 3) * GPB + lm] = w4.w;
    }
    __syncthreads();

#pragma unroll
    for (int kc = 0; kc < 16; kc++) {
        // prefetch next stage (LDG in flight under the FMA block)
        if (kc < 15) {
            a4 = ga[4 * (kc + 1)];
            w4 = gw[4 * (kc + 1)];
        }

        const float* A = AsD[kc & 1];
        const float* B = Bs[kc & 1];
#pragma unroll
        for (int kk = 0; kk < 16; kk++) {
            ulonglong2 d01 = *(const ulonglong2*)&A[kk * GPA + 8 * ty];       // {a0,a0},{a1,a1}
            ulonglong2 d23 = *(const ulonglong2*)&A[kk * GPA + 8 * ty + 4];   // {a2,a2},{a3,a3}
            ulonglong2 bb  = *(const ulonglong2*)&B[kk * GPB + 4 * tx];       // {b0,b1},{b2,b3}
            acc[0][0] = fma2_(d01.x, bb.x, acc[0][0]);
            acc[0][1] = fma2_(d01.x, bb.y, acc[0][1]);
            acc[1][0] = fma2_(d01.y, bb.x, acc[1][0]);
            acc[1][1] = fma2_(d01.y, bb.y, acc[1][1]);
            acc[2][0] = fma2_(d23.x, bb.x, acc[2][0]);
            acc[2][1] = fma2_(d23.x, bb.y, acc[2][1]);
            acc[3][0] = fma2_(d23.y, bb.x, acc[3][0]);
            acc[3][1] = fma2_(d23.y, bb.y, acc[3][1]);
        }

        if (kc < 15) {
            float* An = AsD[(kc + 1) & 1]; float* Bn = Bs[(kc + 1) & 1];
            *(float2*)&An[(lq + 0) * GPA + 2 * lm] = make_float2(a4.x, a4.x);
            *(float2*)&An[(lq + 1) * GPA + 2 * lm] = make_float2(a4.y, a4.y);
            *(float2*)&An[(lq + 2) * GPA + 2 * lm] = make_float2(a4.z, a4.z);
            *(float2*)&An[(lq + 3) * GPA + 2 * lm] = make_float2(a4.w, a4.w);
            Bn[(lq + 0) * GPB + lm] = w4.x;
            Bn[(lq + 1) * GPB + lm] = w4.y;
            Bn[(lq + 2) * GPB + lm] = w4.z;
            Bn[(lq + 3) * GPB + lm] = w4.w;
            __syncthreads();
        }
    }

    // epilogue: 4 STG.128 of partials
    float* dst = &g_part[s][pp * 131072 + (size_t)(b0 + 4 * ty) * 512 + o0 + 4 * tx];
#pragma unroll
    for (int i = 0; i < 4; i++) {
        float4 o;
        o.x = __uint_as_float((unsigned)(acc[i][0]));
        o.y = __uint_as_float((unsigned)(acc[i][0] >> 32));
        o.z = __uint_as_float((unsigned)(acc[i][1]));
        o.w = __uint_as_float((unsigned)(acc[i][1] >> 32));
        *(float4*)(dst + (size_t)i * 512) = o;
    }
}

__global__ void k_reduce(float* __restrict__ out) {
    int idx = blockIdx.x * 256 + threadIdx.x;   // < 262144
    // Fixed summation order -> deterministic
    out[idx] = (g_part[0][idx] + g_part[1][idx]) + (g_part[2][idx] + g_part[3][idx]);
}

// ---------------------------------------------------------------------------

extern "C" void kernel_launch(void* const* d_in, const int* in_sizes, int n_in,
                              void* d_out, int out_size) {
    const float* x  = (const float*)d_in[0];
    const float* W  = (const float*)d_in[1];
    const float* B  = (const float*)d_in[2];
    const float* Wr = (const float*)d_in[3];
    const float* Wi = (const float*)d_in[4];
    float* out = (float*)d_out;

    cudaFuncSetAttribute(k_main, cudaFuncAttributeMaxDynamicSharedMemorySize, SMEM_MAIN);

    k_init_lut<<<18, 256>>>();
    k_init_rb<<<1024, 256>>>(W, B);
    k_main<<<dim3(4, 32, 2), 256, SMEM_MAIN>>>(x);
    k_comb<<<512, 256>>>();
    k_gemm3<<<dim3(4, 8, 8), 256>>>(Wr, Wi);
    k_reduce<<<1024, 256>>>(out);
}

// round 7
// speedup vs baseline: 1.7168x; 1.7168x over previous
#include <cuda_runtime.h>

// ---------------------------------------------------------------------------
// ResonantComplexProjection
//   theta[b,n,i] = x[b,i] / (1+|W[n,i]|) + B[n,i]
//   idx = floor(theta * 4096/2pi) mod 4096   (LUT sin/cos, 4096 entries)
//   cos_sum[b,n] = sum_i cos_lut[idx];  sin_sum likewise
//   real = cos_sum @ Wr^T ; imag = sin_sum @ Wi^T
// Shapes: batch=256, in_f=512, n_neur=1024, out_f=512
// ---------------------------------------------------------------------------

#define LUT_HALF 4608                 // table covers k in [-4608, 4608)
#define LUT_N    (2 * LUT_HALF)       // 9216 entries (float2: sin, cos)
#define SMEM_MAIN (LUT_N * 8 + 8192)  // 72KB LUT + 8KB x tile = 81920 B

static __device__ float4 g_lut4[LUT_N / 2];       // 2 (sin,cos) entries per float4
static __device__ float2 g_rs[256 * 1024];        // [ipair][n] -> {S/(1+|W|)}
static __device__ float2 g_bs[256 * 1024];        // [ipair][n] -> {S*B - 0.5}
static __device__ float2 g_sums[2 * 256 * 1024];  // [half][b][n] -> (sin_sum, cos_sum)
static __device__ float  g_A[2 * 262144];         // [p][b][k]: p0=cos, p1=sin
static __device__ float  g_part[8][262144];       // [ksplit][p*131072 + b*512 + o]

// ---------------------------------------------------------------------------
// Init kernels
// ---------------------------------------------------------------------------

__global__ void k_init_lut() {
    int t = blockIdx.x * 256 + threadIdx.x;       // < 4608
    const float step = (float)(6.283185307179586476925287 / 4096.0);
    int k0 = 2 * t - LUT_HALF;
    int j0 = k0 & 4095;                            // floor-mod 4096 (matches Python %)
    int j1 = (k0 + 1) & 4095;
    float a0 = (float)j0 * step;
    float a1 = (float)j1 * step;
    float4 e;
    e.x = sinf(a0); e.y = cosf(a0);
    e.z = sinf(a1); e.w = cosf(a1);
    g_lut4[t] = e;
}

__global__ void k_init_rb(const float* __restrict__ W, const float* __restrict__ B) {
    int e = blockIdx.x * 256 + threadIdx.x;       // < 262144
    int n  = e & 1023;
    int ip = e >> 10;
    const float S = (float)(4096.0 / 6.283185307179586476925287);
    float2 w = ((const float2*)(W + n * 512))[ip];
    float2 b = ((const float2*)(B + n * 512))[ip];
    float2 rs, bs;
    rs.x = S / (1.0f + fabsf(w.x));
    rs.y = S / (1.0f + fabsf(w.y));
    bs.x = S * b.x - 0.5f;                        // fold floor(v)=round(v-0.5) shift in
    bs.y = S * b.y - 0.5f;
    g_rs[e] = rs;
    g_bs[e] = bs;
}

// ---------------------------------------------------------------------------
// Packed f32x2 helpers (used by k_main only)
// ---------------------------------------------------------------------------

__device__ __forceinline__ unsigned long long fma2_(unsigned long long a,
                                                    unsigned long long b,
                                                    unsigned long long c) {
    unsigned long long d;
    asm("fma.rn.f32x2 %0, %1, %2, %3;" : "=l"(d) : "l"(a), "l"(b), "l"(c));
    return d;
}
__device__ __forceinline__ unsigned long long add2_(unsigned long long a,
                                                    unsigned long long b) {
    unsigned long long d;
    asm("add.rn.f32x2 %0, %1, %2;" : "=l"(d) : "l"(a), "l"(b));
    return d;
}
__device__ __forceinline__ unsigned long long lds64_(unsigned a) {
    unsigned long long v;
    asm("ld.shared.b64 %0, [%1];" : "=l"(v) : "r"(a));
    return v;
}

// ---------------------------------------------------------------------------
// Main kernel (UNCHANGED — proven): grid (4 n-tiles, 32 b-groups, 2 i-halves).
// Magic-number floor + extended shared LUT; packed f32x2 accumulation.
// ---------------------------------------------------------------------------

__global__ __launch_bounds__(256, 2) void k_main(const float* __restrict__ x) {
    extern __shared__ unsigned char smem[];
    float4* lut4 = (float4*)smem;
    unsigned long long* xs2 = (unsigned long long*)(smem + LUT_N * 8);  // [8 b][128 ipair]

    const int tid = threadIdx.x;
    const int nt = blockIdx.x, bg = blockIdx.y, h = blockIdx.z;

#pragma unroll
    for (int t = 0; t < (LUT_N / 2) / 256; t++)        // stage 72KB LUT
        lut4[tid + t * 256] = g_lut4[tid + t * 256];

    const unsigned long long* xg = (const unsigned long long*)x;
#pragma unroll
    for (int t = 0; t < 4; t++) {
        int e = tid + t * 256;
        int lb = e >> 7, ipl = e & 127;
        xs2[e] = xg[(bg * 8 + lb) * 256 + h * 128 + ipl];
    }
    __syncthreads();

    const int n = (nt << 8) + tid;
    const unsigned long long* rsp =
        ((const unsigned long long*)g_rs) + (size_t)(h * 128) * 1024 + n;
    const unsigned long long* bsp =
        ((const unsigned long long*)g_bs) + (size_t)(h * 128) * 1024 + n;

    const unsigned cbase =
        (unsigned)__cvta_generic_to_shared(smem) + (unsigned)(LUT_HALF * 8) - 0x5A000000u;
    const unsigned long long MAGIC2 = 0x4B4000004B400000ULL;

    unsigned long long acc[8];
#pragma unroll
    for (int b = 0; b < 8; b++) acc[b] = 0ULL;

#pragma unroll 2
    for (int ip = 0; ip < 128; ip++) {
        unsigned long long rs2 = __ldg(rsp + ip * 1024);
        unsigned long long bs2 = __ldg(bsp + ip * 1024);
#pragma unroll
        for (int b = 0; b < 8; b++) {
            unsigned long long xp = xs2[b * 128 + ip];
            unsigned long long w  = add2_(fma2_(xp, rs2, bs2), MAGIC2);
            unsigned lo, hi;
            asm("mov.b64 {%0, %1}, %2;" : "=r"(lo), "=r"(hi) : "l"(w));
            unsigned long long e0 = lds64_(lo * 8u + cbase);
            unsigned long long e1 = lds64_(hi * 8u + cbase);
            acc[b] = add2_(acc[b], e0);
            acc[b] = add2_(acc[b], e1);
        }
    }

    unsigned long long* sp =
        ((unsigned long long*)g_sums) + (size_t)h * 262144 + (size_t)(bg * 8) * 1024 + n;
#pragma unroll
    for (int b = 0; b < 8; b++) sp[b * 1024] = acc[b];
}

// ---------------------------------------------------------------------------
// k_comb: combine the two i-half partials ONCE and split into cos/sin planes.
// ---------------------------------------------------------------------------

__global__ void k_comb() {
    int e = blockIdx.x * 256 + threadIdx.x;            // < 131072, 2 entries each
    float4 q0 = ((const float4*)g_sums)[e];            // h0: {s0,c0,s1,c1}
    float4 q1 = ((const float4*)(g_sums + 262144))[e]; // h1
    ((float2*)g_A)[e]            = make_float2(q0.y + q1.y, q0.w + q1.w); // cos
    ((float2*)(g_A + 262144))[e] = make_float2(q0.x + q1.x, q0.z + q1.z); // sin
}

// ---------------------------------------------------------------------------
// k_gemm4: R4's proven skeleton + (a) pre-combined A plane, (b) 8 K-splits,
// (c) register-prefetch double buffer with ONE sync per BK-chunk and
// `#pragma unroll 1` outer loop (small body — avoids R5's I-cache/spill blowup).
//   Block: 64x64 tile, plane p, K-split of 128.  grid (4,8,16) = 512 blocks.
//   Thread: 4x4 scalar microtile -> 2 LDS.128 per 16 FFMA.
// ---------------------------------------------------------------------------

#define BK 16
#define LDP 68    // smem row stride in floats (float4-aligned)

__global__ __launch_bounds__(256, 3) void k_gemm4(const float* __restrict__ Wr,
                                                  const float* __restrict__ Wi) {
    __shared__ float As[2][BK][LDP];
    __shared__ float Bs[2][BK][LDP];

    const int tid = threadIdx.x;
    const int b0 = blockIdx.x << 6;
    const int o0 = blockIdx.y << 6;
    const int z  = blockIdx.z;
    const int pp = z >> 3;               // 0=real(cos), 1=imag(sin)
    const int s  = z & 7;                // K-split (128 each)

    const float* Ap = g_A + pp * 262144;
    const float* Wp = pp ? Wi : Wr;

    const int tx = tid & 15, ty = tid >> 4;
    const int lk = tid & 15;             // k within chunk
    const int lm = tid >> 4;             // base row 0..15 (4 strided rows)
    const int kbase = s << 7;

    float ar[4], br[4];
    // --- stage 0 global loads + smem fill ---
#pragma unroll
    for (int t = 0; t < 4; t++) {
        ar[t] = Ap[(size_t)(b0 + lm + t * 16) * 1024 + kbase + lk];
        br[t] = Wp[(size_t)(o0 + lm + t * 16) * 1024 + kbase + lk];
    }
#pragma unroll
    for (int t = 0; t < 4; t++) {
        As[0][lk][lm + t * 16] = ar[t];
        Bs[0][lk][lm + t * 16] = br[t];
    }
    __syncthreads();

    float acc[4][4] = {};

#pragma unroll 1
    for (int kc = 0; kc < 8; kc++) {
        const int cur = kc & 1;
        // prefetch next chunk into registers (in flight under FMA block)
        if (kc < 7) {
            const int k0 = kbase + ((kc + 1) << 4);
#pragma unroll
            for (int t = 0; t < 4; t++) {
                ar[t] = Ap[(size_t)(b0 + lm + t * 16) * 1024 + k0 + lk];
                br[t] = Wp[(size_t)(o0 + lm + t * 16) * 1024 + k0 + lk];
            }
        }
#pragma unroll
        for (int kk = 0; kk < BK; kk++) {
            float4 a4 = *(const float4*)&As[cur][kk][ty << 2];  // warp broadcast
            float4 b4 = *(const float4*)&Bs[cur][kk][tx << 2];
            float av[4] = {a4.x, a4.y, a4.z, a4.w};
            float bv[4] = {b4.x, b4.y, b4.z, b4.w};
#pragma unroll
            for (int i = 0; i < 4; i++)
#pragma unroll
                for (int j = 0; j < 4; j++)
                    acc[i][j] = fmaf(av[i], bv[j], acc[i][j]);
        }
        if (kc < 7) {
            const int nxt = cur ^ 1;      // other buffer: safe to fill pre-sync
#pragma unroll
            for (int t = 0; t < 4; t++) {
                As[nxt][lk][lm + t * 16] = ar[t];
                Bs[nxt][lk][lm + t * 16] = br[t];
            }
            __syncthreads();              // one barrier per chunk
        }
    }

    float* dst = &g_part[s][pp * 131072 + (size_t)(b0 + (ty << 2)) * 512 + o0 + (tx << 2)];
#pragma unroll
    for (int i = 0; i < 4; i++)
        *(float4*)(dst + (size_t)i * 512) =
            make_float4(acc[i][0], acc[i][1], acc[i][2], acc[i][3]);
}

__global__ void k_reduce(float* __restrict__ out) {
    int idx = blockIdx.x * 256 + threadIdx.x;   // < 262144
    // Fixed summation order -> deterministic
    float a = (g_part[0][idx] + g_part[1][idx]) + (g_part[2][idx] + g_part[3][idx]);
    float b = (g_part[4][idx] + g_part[5][idx]) + (g_part[6][idx] + g_part[7][idx]);
    out[idx] = a + b;
}

// ---------------------------------------------------------------------------

extern "C" void kernel_launch(void* const* d_in, const int* in_sizes, int n_in,
                              void* d_out, int out_size) {
    const float* x  = (const float*)d_in[0];
    const float* W  = (const float*)d_in[1];
    const float* B  = (const float*)d_in[2];
    const float* Wr = (const float*)d_in[3];
    const float* Wi = (const float*)d_in[4];
    float* out = (float*)d_out;

    cudaFuncSetAttribute(k_main, cudaFuncAttributeMaxDynamicSharedMemorySize, SMEM_MAIN);

    k_init_lut<<<18, 256>>>();
    k_init_rb<<<1024, 256>>>(W, B);
    k_main<<<dim3(4, 32, 2), 256, SMEM_MAIN>>>(x);
    k_comb<<<512, 256>>>();
    k_gemm4<<<dim3(4, 8, 16), 256>>>(Wr, Wi);
    k_reduce<<<1024, 256>>>(out);
}